// round 9
// baseline (speedup 1.0000x reference)
#include <cuda_runtime.h>
#include <cstdint>

#define Bb 8
#define Tt 2048
#define Cc 1024
#define HS 64
#define CH 4              // key-tiles (128 keys) per split-KV chunk
#define NSLOT 4
#define WPB 40            // sum_{rb=0}^{15} ceil((rb+1)/4)

__device__ __align__(16) float g_Q[Bb*Tt*HS];
__device__ __align__(16) float g_K[Bb*Tt*HS];      // stored tf32-rounded
__device__ __align__(16) float g_V[Bb*Tt*HS];      // stored tf32-rounded
__device__ __align__(16) float g_Op[NSLOT*Bb*Tt*HS];
__device__ __align__(16) float g_Lp[NSLOT*Bb*Tt];
__device__ __align__(16) uint32_t g_Bpk[64 * 3072]; // 64 chunks x 192 n x 16 perm-k words

__device__ __forceinline__ uint32_t tf32r(float f) {
    uint32_t r; asm("cvt.rna.tf32.f32 %0, %1;" : "=r"(r) : "f"(f)); return r;
}
__device__ __forceinline__ float ex2f(float x) {
    float r; asm("ex2.approx.f32 %0, %1;" : "=f"(r) : "f"(x)); return r;
}
__device__ __forceinline__ void mma8(float4& d, uint32_t a0, uint32_t a1, uint32_t a2, uint32_t a3,
                                     uint32_t b0, uint32_t b1) {
    asm("mma.sync.aligned.m16n8k8.row.col.f32.tf32.tf32.f32 "
        "{%0,%1,%2,%3}, {%4,%5,%6,%7}, {%8,%9}, {%0,%1,%2,%3};"
        : "+f"(d.x), "+f"(d.y), "+f"(d.z), "+f"(d.w)
        : "r"(a0), "r"(a1), "r"(a2), "r"(a3), "r"(b0), "r"(b1));
}
__device__ __forceinline__ uint32_t smem_u32(const void* p) {
    uint32_t a;
    asm("{ .reg .u64 t; cvta.to.shared.u64 t, %1; cvt.u32.u64 %0, t; }" : "=r"(a) : "l"(p));
    return a;
}
__device__ __forceinline__ void cpa16(uint32_t dst, const void* src) {
    asm volatile("cp.async.cg.shared.global [%0], [%1], 16;" :: "r"(dst), "l"(src));
}
#define CP_COMMIT() asm volatile("cp.async.commit_group;" ::: "memory")
#define CP_WAIT0()  asm volatile("cp.async.wait_group 0;" ::: "memory")

// ============================================================================
// Prep: permuted tf32 weight image. g_Bpk[ch][n][t*4+q] = tf32(W[ch*16+t+4q][n&63])
// so a fragment thread's 4 needed k-values per uint4 are contiguous.
// ============================================================================
__global__ __launch_bounds__(256) void prep_b(
    const float* __restrict__ Wq, const float* __restrict__ Wk, const float* __restrict__ Wv)
{
    const int ch = blockIdx.x;
    #pragma unroll
    for (int i = 0; i < 12; i++) {
        const int idx = threadIdx.x + i * 256;     // 0..3071
        const int n = idx >> 4, wd = idx & 15;
        const int t = wd >> 2, q = wd & 3;
        const int k = ch * 16 + t + 4 * q;
        const float* W = (n < 64) ? Wq : (n < 128) ? Wk : Wv;
        g_Bpk[ch * 3072 + idx] = tf32r(W[(size_t)k * HS + (n & 63)]);
    }
}

// ============================================================================
// Fused QKV: CTA 64x192, BK=16, 8 warps (2m x 4n), warp tile 32x48.
// Fragment-native layouts: every A/B fragment load is one LDS.128.
// B staged by cp.async from g_Bpk; A staged LDG.128 + 4 scalar STS (stride 20
// rows: conflict-free). Ping-pong, 1 sync/iter, 2 CTAs/SM.
// ============================================================================
#define SA 20
#define SB 20
__global__ __launch_bounds__(256, 2) void qkv_mma(const float* __restrict__ x)
{
    __shared__ uint32_t Af[2][64 * SA];
    __shared__ uint32_t Bf[2][192 * SB];
    const int tid = threadIdx.x;
    const int w = tid >> 5, lane = tid & 31;
    const int g = lane >> 2, t = lane & 3;
    const int wm = w >> 2, wn = w & 3;
    const int m0 = blockIdx.x * 64;

    float4 acc[2][6];
    #pragma unroll
    for (int i = 0; i < 2; i++)
        #pragma unroll
        for (int j = 0; j < 6; j++) acc[i][j] = make_float4(0.f, 0.f, 0.f, 0.f);

    const int ar = tid >> 2, aq0 = tid & 3;
    const bool bldr = (tid < 192);
    const uint32_t bdst0 = smem_u32(&Bf[0][0]) + (uint32_t)(tid * SB) * 4;
    const uint32_t bdst1 = smem_u32(&Bf[1][0]) + (uint32_t)(tid * SB) * 4;
    const uint32_t* bsrc = g_Bpk + tid * 16;

    // prologue: B chunk 0 -> Bf[0]; A chunk 0 -> regs
    if (bldr) {
        #pragma unroll
        for (int j = 0; j < 4; j++) cpa16(bdst0 + j * 16, bsrc + j * 4);
    }
    CP_COMMIT();
    float4 a_s = *(const float4*)(x + (size_t)(m0 + ar) * Cc + aq0 * 4);

    #pragma unroll 1
    for (int ch = 0; ch < 64; ch++) {
        const int st = ch & 1;
        uint32_t* A = Af[st];
        A[ar * SA + 0 + aq0]  = tf32r(a_s.x);
        A[ar * SA + 4 + aq0]  = tf32r(a_s.y);
        A[ar * SA + 8 + aq0]  = tf32r(a_s.z);
        A[ar * SA + 12 + aq0] = tf32r(a_s.w);
        CP_WAIT0();
        __syncthreads();
        if (ch < 63) {
            if (bldr) {
                const uint32_t* src = bsrc + (ch + 1) * 3072;
                const uint32_t dst = st ? bdst0 : bdst1;
                #pragma unroll
                for (int j = 0; j < 4; j++) cpa16(dst + j * 16, src + j * 4);
            }
            CP_COMMIT();
            a_s = *(const float4*)(x + (size_t)(m0 + ar) * Cc + (ch + 1) * 16 + aq0 * 4);
        }
        // fragments: uint4 = k in {t, t+4, t+8, t+12} = (kk0.b0, kk0.b1, kk1.b0, kk1.b1)
        const uint32_t* Ab = Af[st] + (wm * 32 + g) * SA + t * 4;
        const uint4 A0a = *(const uint4*)(Ab);                 // sub0, row g
        const uint4 A8a = *(const uint4*)(Ab + 8 * SA);        // sub0, row g+8
        const uint4 A0b = *(const uint4*)(Ab + 16 * SA);       // sub1, row g
        const uint4 A8b = *(const uint4*)(Ab + 24 * SA);       // sub1, row g+8
        const uint32_t* Bp = Bf[st] + (wn * 48 + g) * SB + t * 4;
        #pragma unroll
        for (int ns = 0; ns < 6; ns++) {
            const uint4 Bv = *(const uint4*)(Bp + ns * 8 * SB);
            mma8(acc[0][ns], A0a.x, A8a.x, A0a.y, A8a.y, Bv.x, Bv.y);   // kk=0
            mma8(acc[0][ns], A0a.z, A8a.z, A0a.w, A8a.w, Bv.z, Bv.w);   // kk=1
            mma8(acc[1][ns], A0b.x, A8b.x, A0b.y, A8b.y, Bv.x, Bv.y);
            mma8(acc[1][ns], A0b.z, A8b.z, A0b.w, A8b.w, Bv.z, Bv.w);
        }
    }
    // epilogue: Q raw; K,V tf32-rounded (attn stages without cvt)
    #pragma unroll
    for (int sub = 0; sub < 2; sub++) {
        #pragma unroll
        for (int ns = 0; ns < 6; ns++) {
            const int cb = wn * 48 + ns * 8;
            float* base = (cb < 64) ? g_Q : (cb < 128) ? g_K : g_V;
            const bool rnd = (cb >= 64);
            const int c = (cb & 63) + 2 * t;
            const size_t r = (size_t)(m0 + wm * 32 + sub * 16 + g);
            float4 v = acc[sub][ns];
            if (rnd) {
                v.x = __uint_as_float(tf32r(v.x)); v.y = __uint_as_float(tf32r(v.y));
                v.z = __uint_as_float(tf32r(v.z)); v.w = __uint_as_float(tf32r(v.w));
            }
            *(float2*)(base + r * HS + c)       = make_float2(v.x, v.y);
            *(float2*)(base + (r + 8) * HS + c) = make_float2(v.z, v.w);
        }
    }
}

// ============================================================================
// Split-KV causal attention (unchanged from R8): fused per-8-key
// S -> softmax -> PV, 2 CTAs/SM, K/V staged raw via cp.async.
// ============================================================================
#define KLDK 68
#define KLDV 72
#define SMEM_ATTN ((128 * KLDK + 128 * KLDV) * 4)

__global__ __launch_bounds__(256, 2) void attn_part(void)
{
    extern __shared__ uint32_t sm[];
    uint32_t* Ks = sm;
    uint32_t* Vs = sm + 128 * KLDK;
    const uint32_t ks_b = smem_u32(Ks), vs_b = smem_u32(Vs);

    const int item = (gridDim.x - 1) - blockIdx.x;
    const int b = item / WPB;
    int r = item % WPB, rb = 0;
    #pragma unroll 1
    while (true) { int n = (rb + CH) >> 2; if (r < n) break; r -= n; rb++; }
    const int chunk = r;
    const int t0 = chunk * CH;
    const int t1 = (t0 + CH < rb + 1) ? (t0 + CH) : (rb + 1);
    const int qbase = rb * 128;

    const int tid = threadIdx.x;
    const int w = tid >> 5, lane = tid & 31;
    const int g = lane >> 2, t = lane & 3;
    const int qrow_lo = qbase + w * 16 + g;
    const int qrow_hi = qrow_lo + 8;

    const float qscale = 1.4426950408889634f / 32.0f;
    uint32_t aq[8][4];
    {
        const float* r0 = g_Q + ((size_t)b * Tt + qrow_lo) * HS;
        const float* r1 = r0 + 8 * HS;
        #pragma unroll
        for (int kk = 0; kk < 8; kk++) {
            aq[kk][0] = tf32r(r0[kk * 8 + t] * qscale);
            aq[kk][1] = tf32r(r1[kk * 8 + t] * qscale);
            aq[kk][2] = tf32r(r0[kk * 8 + t + 4] * qscale);
            aq[kk][3] = tf32r(r1[kk * 8 + t + 4] * qscale);
        }
    }

    float4 acc_o[8];
    #pragma unroll
    for (int i = 0; i < 8; i++) acc_o[i] = make_float4(0.f, 0.f, 0.f, 0.f);
    float lsum_lo = 0.f, lsum_hi = 0.f;

    const float* Kg = g_K + (size_t)b * Tt * HS;
    const float* Vg = g_V + (size_t)b * Tt * HS;
    const int srcq0 = (lane & ~3) | (t >> 1);
    const int srcq1 = srcq0 | 2;
    const bool odd = (t & 1);

    #pragma unroll 1
    for (int tt = t0; tt < t1; tt++) {
        const int j0 = tt * 128;
        __syncthreads();
        #pragma unroll
        for (int i = 0; i < 8; i++) {
            int u = tid + i * 256;
            int rr = u >> 4, c = (u & 15) * 4;
            cpa16(ks_b + (uint32_t)(rr * KLDK + c) * 4, Kg + (size_t)(j0 + rr) * HS + c);
            cpa16(vs_b + (uint32_t)(rr * KLDV + c) * 4, Vg + (size_t)(j0 + rr) * HS + c);
        }
        CP_COMMIT();
        CP_WAIT0();
        __syncthreads();

        const bool last_tile = (tt == rb);
        #pragma unroll 1
        for (int ns = 0; ns < 16; ns++) {
            float4 cs = make_float4(0.f, 0.f, 0.f, 0.f);
            #pragma unroll
            for (int kk = 0; kk < 8; kk++) {
                uint32_t b0 = Ks[(ns * 8 + g) * KLDK + kk * 8 + t];
                uint32_t b1 = Ks[(ns * 8 + g) * KLDK + kk * 8 + t + 4];
                mma8(cs, aq[kk][0], aq[kk][1], aq[kk][2], aq[kk][3], b0, b1);
            }
            float px = ex2f(cs.x), py = ex2f(cs.y), pz = ex2f(cs.z), pw = ex2f(cs.w);
            if (last_tile) {
                const int cx = j0 + ns * 8 + 2 * t, cy = cx + 1;
                if (cx > qrow_lo) px = 0.f;
                if (cy > qrow_lo) py = 0.f;
                if (cx > qrow_hi) pz = 0.f;
                if (cy > qrow_hi) pw = 0.f;
            }
            uint32_t ux = tf32r(px), uy = tf32r(py), uz = tf32r(pz), uw = tf32r(pw);
            lsum_lo += __uint_as_float(ux) + __uint_as_float(uy);
            lsum_hi += __uint_as_float(uz) + __uint_as_float(uw);
            uint32_t xA = __shfl_sync(0xffffffffu, ux, srcq0);
            uint32_t yA = __shfl_sync(0xffffffffu, uy, srcq0);
            uint32_t zA = __shfl_sync(0xffffffffu, uz, srcq0);
            uint32_t wA = __shfl_sync(0xffffffffu, uw, srcq0);
            uint32_t xB = __shfl_sync(0xffffffffu, ux, srcq1);
            uint32_t yB = __shfl_sync(0xffffffffu, uy, srcq1);
            uint32_t zB = __shfl_sync(0xffffffffu, uz, srcq1);
            uint32_t wB = __shfl_sync(0xffffffffu, uw, srcq1);
            uint32_t a0 = odd ? yA : xA;
            uint32_t a1 = odd ? wA : zA;
            uint32_t a2 = odd ? yB : xB;
            uint32_t a3 = odd ? wB : zB;
            #pragma unroll
            for (int ns2 = 0; ns2 < 8; ns2++) {
                uint32_t b0 = Vs[(ns * 8 + t) * KLDV + ns2 * 8 + g];
                uint32_t b1 = Vs[(ns * 8 + t + 4) * KLDV + ns2 * 8 + g];
                mma8(acc_o[ns2], a0, a1, a2, a3, b0, b1);
            }
        }
    }

    float llo = lsum_lo;
    llo += __shfl_xor_sync(0xffffffffu, llo, 1);
    llo += __shfl_xor_sync(0xffffffffu, llo, 2);
    float lhi = lsum_hi;
    lhi += __shfl_xor_sync(0xffffffffu, lhi, 1);
    lhi += __shfl_xor_sync(0xffffffffu, lhi, 2);

    float* baseo = g_Op + (((size_t)chunk * Bb + b) * Tt + qrow_lo) * HS;
    #pragma unroll
    for (int ns2 = 0; ns2 < 8; ns2++) {
        *(float2*)(baseo + ns2 * 8 + 2 * t)          = make_float2(acc_o[ns2].x, acc_o[ns2].y);
        *(float2*)(baseo + 8 * HS + ns2 * 8 + 2 * t) = make_float2(acc_o[ns2].z, acc_o[ns2].w);
    }
    if (t == 0) {
        g_Lp[((size_t)chunk * Bb + b) * Tt + qrow_lo] = llo;
        g_Lp[((size_t)chunk * Bb + b) * Tt + qrow_hi] = lhi;
    }
}

// ============================================================================
// Combine (unchanged from R8): float4/thread, <=4 slots.
// ============================================================================
__global__ __launch_bounds__(256) void attn_combine(float* __restrict__ out)
{
    const int idx4 = blockIdx.x * 256 + threadIdx.x;
    const int row  = idx4 >> 4;
    const int d4   = (idx4 & 15) * 4;
    const int trow = row & (Tt - 1);
    const int b    = row >> 11;
    const int rb   = trow >> 7;
    const int nch  = (rb + CH) >> 2;

    float4 o = make_float4(0.f, 0.f, 0.f, 0.f);
    float l = 0.f;
    #pragma unroll
    for (int s = 0; s < NSLOT; s++) {
        if (s < nch) {
            float4 v = *(const float4*)(g_Op + (((size_t)s * Bb + b) * Tt + trow) * HS + d4);
            o.x += v.x; o.y += v.y; o.z += v.z; o.w += v.w;
            l += g_Lp[((size_t)s * Bb + b) * Tt + trow];
        }
    }
    const float rl = 1.0f / l;
    *(float4*)(out + (size_t)row * HS + d4) =
        make_float4(o.x * rl, o.y * rl, o.z * rl, o.w * rl);
}

// ============================================================================
extern "C" void kernel_launch(void* const* d_in, const int* in_sizes, int n_in,
                              void* d_out, int out_size)
{
    const float* x  = (const float*)d_in[0];
    const float* Wq = (const float*)d_in[1];
    const float* Wk = (const float*)d_in[2];
    const float* Wv = (const float*)d_in[3];
    float* out = (float*)d_out;

    prep_b<<<64, 256>>>(Wq, Wk, Wv);
    qkv_mma<<<(Bb * Tt) / 64, 256>>>(x);

    cudaFuncSetAttribute(attn_part, cudaFuncAttributeMaxDynamicSharedMemorySize, SMEM_ATTN);
    attn_part<<<Bb * WPB, 256, SMEM_ATTN>>>();

    attn_combine<<<(Bb * Tt * (HS / 4)) / 256, 256>>>(out);
}

// round 10
// speedup vs baseline: 1.1782x; 1.1782x over previous
#include <cuda_runtime.h>
#include <cstdint>

#define Bb 8
#define Tt 2048
#define Cc 1024
#define HS 64
#define CH 4              // key-tiles (128 keys) per split-KV chunk
#define NSLOT 4
#define WPB 40            // sum_{rb=0}^{15} ceil((rb+1)/4)

__device__ __align__(16) float g_Q[Bb*Tt*HS];
__device__ __align__(16) float g_K[Bb*Tt*HS];      // tf32-rounded, k-permuted
__device__ __align__(16) float g_V[Bb*Tt*HS];      // tf32-rounded, d-permuted
__device__ __align__(16) float g_Op[NSLOT*Bb*Tt*HS];
__device__ __align__(16) float g_Lp[NSLOT*Bb*Tt];

__device__ __forceinline__ uint32_t tf32r(float f) {
    uint32_t r; asm("cvt.rna.tf32.f32 %0, %1;" : "=r"(r) : "f"(f)); return r;
}
__device__ __forceinline__ float ex2f(float x) {
    float r; asm("ex2.approx.f32 %0, %1;" : "=f"(r) : "f"(x)); return r;
}
__device__ __forceinline__ void mma8(float4& d, uint32_t a0, uint32_t a1, uint32_t a2, uint32_t a3,
                                     uint32_t b0, uint32_t b1) {
    asm("mma.sync.aligned.m16n8k8.row.col.f32.tf32.tf32.f32 "
        "{%0,%1,%2,%3}, {%4,%5,%6,%7}, {%8,%9}, {%0,%1,%2,%3};"
        : "+f"(d.x), "+f"(d.y), "+f"(d.z), "+f"(d.w)
        : "r"(a0), "r"(a1), "r"(a2), "r"(a3), "r"(b0), "r"(b1));
}
__device__ __forceinline__ uint4 cvt4(float4 v) {
    return make_uint4(tf32r(v.x), tf32r(v.y), tf32r(v.z), tf32r(v.w));
}
__device__ __forceinline__ uint32_t smem_u32(const void* p) {
    uint32_t a;
    asm("{ .reg .u64 t; cvta.to.shared.u64 t, %1; cvt.u32.u64 %0, t; }" : "=r"(a) : "l"(p));
    return a;
}
__device__ __forceinline__ void cpa16(uint32_t dst, const void* src) {
    asm volatile("cp.async.cg.shared.global [%0], [%1], 16;" :: "r"(dst), "l"(src));
}
#define CP_COMMIT() asm volatile("cp.async.commit_group;" ::: "memory")
#define CP_WAIT0()  asm volatile("cp.async.wait_group 0;" ::: "memory")

// word position of head-dim d within a permuted K row (for LDS.128 fragments)
__device__ __forceinline__ int permk(int d) {
    return ((d >> 4) << 4) | ((d & 3) << 2) | ((d >> 2) & 3);
}
// word position of head-dim d within a permuted V row
__device__ __forceinline__ int permv(int d) {
    return ((d & 7) << 3) | (d >> 3);
}

// ============================================================================
// Fused QKV (R8 body, measured 68.6us): CTA 64x192, BK=16, 8 warps (2m x 4n),
// warp tile 32x48, ping-pong smem, 1 sync/iter, 2 CTAs/SM.
// Epilogue: Q raw; K/V tf32-rounded AND fragment-permuted for attn.
// ============================================================================
#define ALD 36
#define BLD 200
__global__ __launch_bounds__(256, 2) void qkv_mma(
    const float* __restrict__ x, const float* __restrict__ Wq,
    const float* __restrict__ Wk, const float* __restrict__ Wv)
{
    __shared__ uint32_t As[2][64 * ALD];
    __shared__ uint32_t Bs[2][16 * BLD];
    const int tid = threadIdx.x;
    const int w = tid >> 5, lane = tid & 31;
    const int g = lane >> 2, t = lane & 3;
    const int wm = w >> 2, wn = w & 3;
    const int m0 = blockIdx.x * 64;

    float4 acc[2][6];
    #pragma unroll
    for (int i = 0; i < 2; i++)
        #pragma unroll
        for (int j = 0; j < 6; j++) acc[i][j] = make_float4(0.f, 0.f, 0.f, 0.f);

    const int ar = tid >> 2, ac = (tid & 3) * 4;
    const int wkr = tid >> 4, wcc = (tid & 15) * 4;

    float4 a_s = *(const float4*)(x + (size_t)(m0 + ar) * Cc + ac);
    float4 q_s = *(const float4*)(Wq + (size_t)wkr * HS + wcc);
    float4 k_s = *(const float4*)(Wk + (size_t)wkr * HS + wcc);
    float4 v_s = *(const float4*)(Wv + (size_t)wkr * HS + wcc);

    #pragma unroll 1
    for (int ch = 0; ch < 64; ch++) {
        const int st = ch & 1;
        *(uint4*)(As[st] + ar * ALD + ac)         = cvt4(a_s);
        *(uint4*)(Bs[st] + wkr * BLD + wcc)       = cvt4(q_s);
        *(uint4*)(Bs[st] + wkr * BLD + 64 + wcc)  = cvt4(k_s);
        *(uint4*)(Bs[st] + wkr * BLD + 128 + wcc) = cvt4(v_s);
        __syncthreads();
        if (ch < 63) {
            const int k0 = (ch + 1) * 16;
            a_s = *(const float4*)(x + (size_t)(m0 + ar) * Cc + k0 + ac);
            q_s = *(const float4*)(Wq + (size_t)(k0 + wkr) * HS + wcc);
            k_s = *(const float4*)(Wk + (size_t)(k0 + wkr) * HS + wcc);
            v_s = *(const float4*)(Wv + (size_t)(k0 + wkr) * HS + wcc);
        }
        #pragma unroll
        for (int kk = 0; kk < 2; kk++) {
            uint32_t a[2][4];
            #pragma unroll
            for (int sub = 0; sub < 2; sub++) {
                const int rbase = (wm * 32 + sub * 16 + g) * ALD + kk * 8;
                a[sub][0] = As[st][rbase + t];
                a[sub][1] = As[st][rbase + 8 * ALD + t];
                a[sub][2] = As[st][rbase + t + 4];
                a[sub][3] = As[st][rbase + 8 * ALD + t + 4];
            }
            #pragma unroll
            for (int ns = 0; ns < 6; ns++) {
                uint32_t b0 = Bs[st][(kk * 8 + t) * BLD + wn * 48 + ns * 8 + g];
                uint32_t b1 = Bs[st][(kk * 8 + t + 4) * BLD + wn * 48 + ns * 8 + g];
                #pragma unroll
                for (int sub = 0; sub < 2; sub++)
                    mma8(acc[sub][ns], a[sub][0], a[sub][1], a[sub][2], a[sub][3], b0, b1);
            }
        }
    }
    #pragma unroll
    for (int sub = 0; sub < 2; sub++) {
        #pragma unroll
        for (int ns = 0; ns < 6; ns++) {
            const int cb = wn * 48 + ns * 8;
            const int c = (cb & 63) + 2 * t;
            const size_t r = (size_t)(m0 + wm * 32 + sub * 16 + g);
            float4 v = acc[sub][ns];
            if (cb < 64) {
                // Q: raw fp32
                *(float2*)(g_Q + r * HS + c)       = make_float2(v.x, v.y);
                *(float2*)(g_Q + (r + 8) * HS + c) = make_float2(v.z, v.w);
            } else if (cb < 128) {
                // K: tf32-rounded, k-permuted row layout
                const int p0 = permk(c), p1 = permk(c + 1);
                g_K[r * HS + p0]       = __uint_as_float(tf32r(v.x));
                g_K[r * HS + p1]       = __uint_as_float(tf32r(v.y));
                g_K[(r + 8) * HS + p0] = __uint_as_float(tf32r(v.z));
                g_K[(r + 8) * HS + p1] = __uint_as_float(tf32r(v.w));
            } else {
                // V: tf32-rounded, d-permuted row layout
                const int p0 = permv(c), p1 = permv(c + 1);
                g_V[r * HS + p0]       = __uint_as_float(tf32r(v.x));
                g_V[r * HS + p1]       = __uint_as_float(tf32r(v.y));
                g_V[(r + 8) * HS + p0] = __uint_as_float(tf32r(v.z));
                g_V[(r + 8) * HS + p1] = __uint_as_float(tf32r(v.w));
            }
        }
    }
}

// ============================================================================
// Split-KV causal attention: fused per-8-key S -> softmax -> PV, 2 CTAs/SM.
// K/V staged raw via cp.async; fragments via LDS.128 on permuted layouts.
// ============================================================================
#define LDK 80
#define LDV 72
#define SMEM_ATTN ((128 * LDK + 128 * LDV) * 4)

__global__ __launch_bounds__(256, 2) void attn_part(void)
{
    extern __shared__ uint32_t sm[];
    uint32_t* Ks = sm;
    uint32_t* Vs = sm + 128 * LDK;
    const uint32_t ks_b = smem_u32(Ks), vs_b = smem_u32(Vs);

    const int item = (gridDim.x - 1) - blockIdx.x;
    const int b = item / WPB;
    int r = item % WPB, rb = 0;
    #pragma unroll 1
    while (true) { int n = (rb + CH) >> 2; if (r < n) break; r -= n; rb++; }
    const int chunk = r;
    const int t0 = chunk * CH;
    const int t1 = (t0 + CH < rb + 1) ? (t0 + CH) : (rb + 1);
    const int qbase = rb * 128;

    const int tid = threadIdx.x;
    const int w = tid >> 5, lane = tid & 31;
    const int g = lane >> 2, t = lane & 3;
    const int qrow_lo = qbase + w * 16 + g;
    const int qrow_hi = qrow_lo + 8;

    const float qscale = 1.4426950408889634f / 32.0f;
    uint32_t aq[8][4];
    {
        const float* r0 = g_Q + ((size_t)b * Tt + qrow_lo) * HS;
        const float* r1 = r0 + 8 * HS;
        #pragma unroll
        for (int kk = 0; kk < 8; kk++) {
            aq[kk][0] = tf32r(r0[kk * 8 + t] * qscale);
            aq[kk][1] = tf32r(r1[kk * 8 + t] * qscale);
            aq[kk][2] = tf32r(r0[kk * 8 + t + 4] * qscale);
            aq[kk][3] = tf32r(r1[kk * 8 + t + 4] * qscale);
        }
    }

    float4 acc_o[8];
    #pragma unroll
    for (int i = 0; i < 8; i++) acc_o[i] = make_float4(0.f, 0.f, 0.f, 0.f);
    float lsum_lo = 0.f, lsum_hi = 0.f;

    const float* Kg = g_K + (size_t)b * Tt * HS;
    const float* Vg = g_V + (size_t)b * Tt * HS;
    const int srcq0 = (lane & ~3) | (t >> 1);
    const int srcq1 = srcq0 | 2;
    const bool odd = (t & 1);

    #pragma unroll 1
    for (int tt = t0; tt < t1; tt++) {
        const int j0 = tt * 128;
        __syncthreads();
        #pragma unroll
        for (int i = 0; i < 8; i++) {
            int u = tid + i * 256;
            int rr = u >> 4, c = (u & 15) * 4;   // 16B chunk c within 64-word row
            cpa16(ks_b + (uint32_t)(rr * LDK + c) * 4, Kg + (size_t)(j0 + rr) * HS + c);
            cpa16(vs_b + (uint32_t)(rr * LDV + c) * 4, Vg + (size_t)(j0 + rr) * HS + c);
        }
        CP_COMMIT();
        CP_WAIT0();
        __syncthreads();

        const bool last_tile = (tt == rb);
        #pragma unroll 1
        for (int ns = 0; ns < 16; ns++) {
            // ---- S subtile: K fragments via 4 conflict-free LDS.128 ----
            float4 cs = make_float4(0.f, 0.f, 0.f, 0.f);
            const uint32_t* kp = Ks + (ns * 8 + g) * LDK + t * 4;
            #pragma unroll
            for (int j = 0; j < 4; j++) {
                const uint4 Kv = *(const uint4*)(kp + j * 16);
                mma8(cs, aq[2*j][0],   aq[2*j][1],   aq[2*j][2],   aq[2*j][3],   Kv.x, Kv.y);
                mma8(cs, aq[2*j+1][0], aq[2*j+1][1], aq[2*j+1][2], aq[2*j+1][3], Kv.z, Kv.w);
            }
            // ---- softmax + mask + tf32 round ----
            float px = ex2f(cs.x), py = ex2f(cs.y), pz = ex2f(cs.z), pw = ex2f(cs.w);
            if (last_tile) {
                const int cx = j0 + ns * 8 + 2 * t, cy = cx + 1;
                if (cx > qrow_lo) px = 0.f;
                if (cy > qrow_lo) py = 0.f;
                if (cx > qrow_hi) pz = 0.f;
                if (cy > qrow_hi) pw = 0.f;
            }
            uint32_t ux = tf32r(px), uy = tf32r(py), uz = tf32r(pz), uw = tf32r(pw);
            lsum_lo += __uint_as_float(ux) + __uint_as_float(uy);
            lsum_hi += __uint_as_float(uz) + __uint_as_float(uw);
            // ---- C-frag -> A-frag ----
            uint32_t xA = __shfl_sync(0xffffffffu, ux, srcq0);
            uint32_t yA = __shfl_sync(0xffffffffu, uy, srcq0);
            uint32_t zA = __shfl_sync(0xffffffffu, uz, srcq0);
            uint32_t wA = __shfl_sync(0xffffffffu, uw, srcq0);
            uint32_t xB = __shfl_sync(0xffffffffu, ux, srcq1);
            uint32_t yB = __shfl_sync(0xffffffffu, uy, srcq1);
            uint32_t zB = __shfl_sync(0xffffffffu, uz, srcq1);
            uint32_t wB = __shfl_sync(0xffffffffu, uw, srcq1);
            uint32_t a0 = odd ? yA : xA;
            uint32_t a1 = odd ? wA : zA;
            uint32_t a2 = odd ? yB : xB;
            uint32_t a3 = odd ? wB : zB;
            // ---- PV: V fragments via 4 LDS.128 (2-way conflict, accepted) ----
            const uint32_t* vpa = Vs + (ns * 8 + t) * LDV + g * 8;
            const uint32_t* vpb = vpa + 4 * LDV;
            const uint4 Va0 = *(const uint4*)(vpa);
            const uint4 Va1 = *(const uint4*)(vpa + 4);
            const uint4 Vb0 = *(const uint4*)(vpb);
            const uint4 Vb1 = *(const uint4*)(vpb + 4);
            mma8(acc_o[0], a0, a1, a2, a3, Va0.x, Vb0.x);
            mma8(acc_o[1], a0, a1, a2, a3, Va0.y, Vb0.y);
            mma8(acc_o[2], a0, a1, a2, a3, Va0.z, Vb0.z);
            mma8(acc_o[3], a0, a1, a2, a3, Va0.w, Vb0.w);
            mma8(acc_o[4], a0, a1, a2, a3, Va1.x, Vb1.x);
            mma8(acc_o[5], a0, a1, a2, a3, Va1.y, Vb1.y);
            mma8(acc_o[6], a0, a1, a2, a3, Va1.z, Vb1.z);
            mma8(acc_o[7], a0, a1, a2, a3, Va1.w, Vb1.w);
        }
    }

    float llo = lsum_lo;
    llo += __shfl_xor_sync(0xffffffffu, llo, 1);
    llo += __shfl_xor_sync(0xffffffffu, llo, 2);
    float lhi = lsum_hi;
    lhi += __shfl_xor_sync(0xffffffffu, lhi, 1);
    lhi += __shfl_xor_sync(0xffffffffu, lhi, 2);

    float* baseo = g_Op + (((size_t)chunk * Bb + b) * Tt + qrow_lo) * HS;
    #pragma unroll
    for (int ns2 = 0; ns2 < 8; ns2++) {
        *(float2*)(baseo + ns2 * 8 + 2 * t)          = make_float2(acc_o[ns2].x, acc_o[ns2].y);
        *(float2*)(baseo + 8 * HS + ns2 * 8 + 2 * t) = make_float2(acc_o[ns2].z, acc_o[ns2].w);
    }
    if (t == 0) {
        g_Lp[((size_t)chunk * Bb + b) * Tt + qrow_lo] = llo;
        g_Lp[((size_t)chunk * Bb + b) * Tt + qrow_hi] = lhi;
    }
}

// ============================================================================
// Combine (R8): float4/thread, <=4 slots.
// ============================================================================
__global__ __launch_bounds__(256) void attn_combine(float* __restrict__ out)
{
    const int idx4 = blockIdx.x * 256 + threadIdx.x;
    const int row  = idx4 >> 4;
    const int d4   = (idx4 & 15) * 4;
    const int trow = row & (Tt - 1);
    const int b    = row >> 11;
    const int rb   = trow >> 7;
    const int nch  = (rb + CH) >> 2;

    float4 o = make_float4(0.f, 0.f, 0.f, 0.f);
    float l = 0.f;
    #pragma unroll
    for (int s = 0; s < NSLOT; s++) {
        if (s < nch) {
            float4 v = *(const float4*)(g_Op + (((size_t)s * Bb + b) * Tt + trow) * HS + d4);
            o.x += v.x; o.y += v.y; o.z += v.z; o.w += v.w;
            l += g_Lp[((size_t)s * Bb + b) * Tt + trow];
        }
    }
    const float rl = 1.0f / l;
    *(float4*)(out + (size_t)row * HS + d4) =
        make_float4(o.x * rl, o.y * rl, o.z * rl, o.w * rl);
}

// ============================================================================
extern "C" void kernel_launch(void* const* d_in, const int* in_sizes, int n_in,
                              void* d_out, int out_size)
{
    const float* x  = (const float*)d_in[0];
    const float* Wq = (const float*)d_in[1];
    const float* Wk = (const float*)d_in[2];
    const float* Wv = (const float*)d_in[3];
    float* out = (float*)d_out;

    qkv_mma<<<(Bb * Tt) / 64, 256>>>(x, Wq, Wk, Wv);

    cudaFuncSetAttribute(attn_part, cudaFuncAttributeMaxDynamicSharedMemorySize, SMEM_ATTN);
    attn_part<<<Bb * WPB, 256, SMEM_ATTN>>>();

    attn_combine<<<(Bb * Tt * (HS / 4)) / 256, 256>>>(out);
}

// round 11
// speedup vs baseline: 1.2617x; 1.0708x over previous
#include <cuda_runtime.h>
#include <cstdint>

#define Bb 8
#define Tt 2048
#define Cc 1024
#define HS 64
#define CH 4              // key-tiles (128 keys) per split-KV chunk
#define NSLOT 4
#define WPB 40            // sum_{rb=0}^{15} ceil((rb+1)/4)

__device__ __align__(16) float g_Q[Bb*Tt*HS];
__device__ __align__(16) float g_K[Bb*Tt*HS];      // tf32-rounded
__device__ __align__(16) float g_V[Bb*Tt*HS];      // tf32-rounded
__device__ __align__(16) float g_Op[NSLOT*Bb*Tt*HS];
__device__ __align__(16) float g_Lp[NSLOT*Bb*Tt];
__device__ __align__(16) uint32_t g_Bpk[64 * 3072]; // 64 k-chunks x 192 n-rows x 16 words

__device__ __forceinline__ uint32_t tf32r(float f) {
    uint32_t r; asm("cvt.rna.tf32.f32 %0, %1;" : "=r"(r) : "f"(f)); return r;
}
__device__ __forceinline__ float ex2f(float x) {
    float r; asm("ex2.approx.f32 %0, %1;" : "=f"(r) : "f"(x)); return r;
}
__device__ __forceinline__ void mma8(float4& d, uint32_t a0, uint32_t a1, uint32_t a2, uint32_t a3,
                                     uint32_t b0, uint32_t b1) {
    asm("mma.sync.aligned.m16n8k8.row.col.f32.tf32.tf32.f32 "
        "{%0,%1,%2,%3}, {%4,%5,%6,%7}, {%8,%9}, {%0,%1,%2,%3};"
        : "+f"(d.x), "+f"(d.y), "+f"(d.z), "+f"(d.w)
        : "r"(a0), "r"(a1), "r"(a2), "r"(a3), "r"(b0), "r"(b1));
}
__device__ __forceinline__ uint32_t smem_u32(const void* p) {
    uint32_t a;
    asm("{ .reg .u64 t; cvta.to.shared.u64 t, %1; cvt.u32.u64 %0, t; }" : "=r"(a) : "l"(p));
    return a;
}
__device__ __forceinline__ void cpa16(uint32_t dst, const void* src) {
    asm volatile("cp.async.cg.shared.global [%0], [%1], 16;" :: "r"(dst), "l"(src));
}
#define CP_COMMIT() asm volatile("cp.async.commit_group;" ::: "memory")
#define CP_WAIT0()  asm volatile("cp.async.wait_group 0;" ::: "memory")

// ============================================================================
// Prep: weights -> permuted + XOR-swizzled tf32 image.
// Word layout of row n (16 words): word[((k&3)^(n&3))*4 + (k>>2)] = W[k][n].
// ============================================================================
__global__ __launch_bounds__(256) void prep_b(
    const float* __restrict__ Wq, const float* __restrict__ Wk, const float* __restrict__ Wv)
{
    const int ch = blockIdx.x;
    #pragma unroll
    for (int i = 0; i < 12; i++) {
        const int idx = threadIdx.x + i * 256;    // 0..3071
        const int n = idx >> 4, wd = idx & 15;
        const int k = ((wd & 3) << 2) | ((wd >> 2) ^ (n & 3));
        const float* W = (n < 64) ? Wq : (n < 128) ? Wk : Wv;
        g_Bpk[ch * 3072 + idx] = tf32r(W[(size_t)(ch * 16 + k) * HS + (n & 63)]);
    }
}

// ============================================================================
// Fused QKV: CTA 64x192, BK=16, 8 warps (2m x 4n), warp tile 32x48.
// XOR-swizzled 16-word rows: every fragment load is one conflict-free LDS.128.
// B staged via cp.async from prepped image (overlapped); A via LDG+cvt+4 STS.
// Ping-pong, 1 sync/iter, 2 CTAs/SM.
// ============================================================================
__global__ __launch_bounds__(256, 2) void qkv_mma(const float* __restrict__ x)
{
    __shared__ uint32_t Af[2][64 * 16];
    __shared__ uint32_t Bf[2][192 * 16];
    const int tid = threadIdx.x;
    const int w = tid >> 5, lane = tid & 31;
    const int g = lane >> 2, t = lane & 3;
    const int wm = w >> 2, wn = w & 3;
    const int m0 = blockIdx.x * 64;

    float4 acc[2][6];
    #pragma unroll
    for (int i = 0; i < 2; i++)
        #pragma unroll
        for (int j = 0; j < 6; j++) acc[i][j] = make_float4(0.f, 0.f, 0.f, 0.f);

    const int ar = tid >> 2, aq0 = tid & 3;
    const int asw = ar & 3;
    const bool bldr = (tid < 192);
    const uint32_t bdst0 = smem_u32(&Bf[0][0]) + (uint32_t)tid * 64;
    const uint32_t bdst1 = smem_u32(&Bf[1][0]) + (uint32_t)tid * 64;
    const uint32_t* bsrc = g_Bpk + tid * 16;

    // prologue
    if (bldr) {
        #pragma unroll
        for (int j = 0; j < 4; j++) cpa16(bdst0 + j * 16, bsrc + j * 4);
    }
    CP_COMMIT();
    float4 a_s = *(const float4*)(x + (size_t)(m0 + ar) * Cc + aq0 * 4);

    const int fsw = ((t ^ (g & 3)) << 2);           // fragment chunk offset
    const int ra = (wm * 32 + g) * 16;              // A row base (words)
    const int rb = (wn * 48 + g) * 16;              // B row base (words)

    #pragma unroll 1
    for (int ch = 0; ch < 64; ch++) {
        const int st = ch & 1;
        {
            uint32_t* A = Af[st] + ar * 16 + aq0;
            A[((0 ^ asw) << 2)] = tf32r(a_s.x);
            A[((1 ^ asw) << 2)] = tf32r(a_s.y);
            A[((2 ^ asw) << 2)] = tf32r(a_s.z);
            A[((3 ^ asw) << 2)] = tf32r(a_s.w);
        }
        CP_WAIT0();
        __syncthreads();
        if (ch < 63) {
            if (bldr) {
                const uint32_t* src = bsrc + (ch + 1) * 3072;
                const uint32_t dst = st ? bdst0 : bdst1;
                #pragma unroll
                for (int j = 0; j < 4; j++) cpa16(dst + j * 16, src + j * 4);
            }
            CP_COMMIT();
            a_s = *(const float4*)(x + (size_t)(m0 + ar) * Cc + (ch + 1) * 16 + aq0 * 4);
        }
        // fragments: uint4 = k in {t, t+4, t+8, t+12}
        const uint32_t* Ap = Af[st];
        const uint4 A0a = *(const uint4*)(Ap + ra + fsw);
        const uint4 A8a = *(const uint4*)(Ap + ra + 8 * 16 + fsw);
        const uint4 A0b = *(const uint4*)(Ap + ra + 16 * 16 + fsw);
        const uint4 A8b = *(const uint4*)(Ap + ra + 24 * 16 + fsw);
        const uint32_t* Bp = Bf[st];
        #pragma unroll
        for (int ns = 0; ns < 6; ns++) {
            const uint4 Bv = *(const uint4*)(Bp + rb + ns * 8 * 16 + fsw);
            mma8(acc[0][ns], A0a.x, A8a.x, A0a.y, A8a.y, Bv.x, Bv.y);   // kk=0
            mma8(acc[0][ns], A0a.z, A8a.z, A0a.w, A8a.w, Bv.z, Bv.w);   // kk=1
            mma8(acc[1][ns], A0b.x, A8b.x, A0b.y, A8b.y, Bv.x, Bv.y);
            mma8(acc[1][ns], A0b.z, A8b.z, A0b.w, A8b.w, Bv.z, Bv.w);
        }
    }
    // epilogue (R8): Q raw; K,V tf32-rounded plain layout
    #pragma unroll
    for (int sub = 0; sub < 2; sub++) {
        #pragma unroll
        for (int ns = 0; ns < 6; ns++) {
            const int cb = wn * 48 + ns * 8;
            float* base = (cb < 64) ? g_Q : (cb < 128) ? g_K : g_V;
            const bool rnd = (cb >= 64);
            const int c = (cb & 63) + 2 * t;
            const size_t r = (size_t)(m0 + wm * 32 + sub * 16 + g);
            float4 v = acc[sub][ns];
            if (rnd) {
                v.x = __uint_as_float(tf32r(v.x)); v.y = __uint_as_float(tf32r(v.y));
                v.z = __uint_as_float(tf32r(v.z)); v.w = __uint_as_float(tf32r(v.w));
            }
            *(float2*)(base + r * HS + c)       = make_float2(v.x, v.y);
            *(float2*)(base + (r + 8) * HS + c) = make_float2(v.z, v.w);
        }
    }
}

// ============================================================================
// Split-KV causal attention (exact R8): fused per-8-key S -> softmax -> PV,
// 2 CTAs/SM, K/V staged raw via cp.async, scalar fragment gathers.
// ============================================================================
#define KLDK 68
#define KLDV 72
#define SMEM_ATTN ((128 * KLDK + 128 * KLDV) * 4)

__global__ __launch_bounds__(256, 2) void attn_part(void)
{
    extern __shared__ uint32_t sm[];
    uint32_t* Ks = sm;
    uint32_t* Vs = sm + 128 * KLDK;
    const uint32_t ks_b = smem_u32(Ks), vs_b = smem_u32(Vs);

    const int item = (gridDim.x - 1) - blockIdx.x;
    const int b = item / WPB;
    int r = item % WPB, rb = 0;
    #pragma unroll 1
    while (true) { int n = (rb + CH) >> 2; if (r < n) break; r -= n; rb++; }
    const int chunk = r;
    const int t0 = chunk * CH;
    const int t1 = (t0 + CH < rb + 1) ? (t0 + CH) : (rb + 1);
    const int qbase = rb * 128;

    const int tid = threadIdx.x;
    const int w = tid >> 5, lane = tid & 31;
    const int g = lane >> 2, t = lane & 3;
    const int qrow_lo = qbase + w * 16 + g;
    const int qrow_hi = qrow_lo + 8;

    const float qscale = 1.4426950408889634f / 32.0f;
    uint32_t aq[8][4];
    {
        const float* r0 = g_Q + ((size_t)b * Tt + qrow_lo) * HS;
        const float* r1 = r0 + 8 * HS;
        #pragma unroll
        for (int kk = 0; kk < 8; kk++) {
            aq[kk][0] = tf32r(r0[kk * 8 + t] * qscale);
            aq[kk][1] = tf32r(r1[kk * 8 + t] * qscale);
            aq[kk][2] = tf32r(r0[kk * 8 + t + 4] * qscale);
            aq[kk][3] = tf32r(r1[kk * 8 + t + 4] * qscale);
        }
    }

    float4 acc_o[8];
    #pragma unroll
    for (int i = 0; i < 8; i++) acc_o[i] = make_float4(0.f, 0.f, 0.f, 0.f);
    float lsum_lo = 0.f, lsum_hi = 0.f;

    const float* Kg = g_K + (size_t)b * Tt * HS;
    const float* Vg = g_V + (size_t)b * Tt * HS;
    const int srcq0 = (lane & ~3) | (t >> 1);
    const int srcq1 = srcq0 | 2;
    const bool odd = (t & 1);

    #pragma unroll 1
    for (int tt = t0; tt < t1; tt++) {
        const int j0 = tt * 128;
        __syncthreads();
        #pragma unroll
        for (int i = 0; i < 8; i++) {
            int u = tid + i * 256;
            int rr = u >> 4, c = (u & 15) * 4;
            cpa16(ks_b + (uint32_t)(rr * KLDK + c) * 4, Kg + (size_t)(j0 + rr) * HS + c);
            cpa16(vs_b + (uint32_t)(rr * KLDV + c) * 4, Vg + (size_t)(j0 + rr) * HS + c);
        }
        CP_COMMIT();
        CP_WAIT0();
        __syncthreads();

        const bool last_tile = (tt == rb);
        #pragma unroll 1
        for (int ns = 0; ns < 16; ns++) {
            float4 cs = make_float4(0.f, 0.f, 0.f, 0.f);
            #pragma unroll
            for (int kk = 0; kk < 8; kk++) {
                uint32_t b0 = Ks[(ns * 8 + g) * KLDK + kk * 8 + t];
                uint32_t b1 = Ks[(ns * 8 + g) * KLDK + kk * 8 + t + 4];
                mma8(cs, aq[kk][0], aq[kk][1], aq[kk][2], aq[kk][3], b0, b1);
            }
            float px = ex2f(cs.x), py = ex2f(cs.y), pz = ex2f(cs.z), pw = ex2f(cs.w);
            if (last_tile) {
                const int cx = j0 + ns * 8 + 2 * t, cy = cx + 1;
                if (cx > qrow_lo) px = 0.f;
                if (cy > qrow_lo) py = 0.f;
                if (cx > qrow_hi) pz = 0.f;
                if (cy > qrow_hi) pw = 0.f;
            }
            uint32_t ux = tf32r(px), uy = tf32r(py), uz = tf32r(pz), uw = tf32r(pw);
            lsum_lo += __uint_as_float(ux) + __uint_as_float(uy);
            lsum_hi += __uint_as_float(uz) + __uint_as_float(uw);
            uint32_t xA = __shfl_sync(0xffffffffu, ux, srcq0);
            uint32_t yA = __shfl_sync(0xffffffffu, uy, srcq0);
            uint32_t zA = __shfl_sync(0xffffffffu, uz, srcq0);
            uint32_t wA = __shfl_sync(0xffffffffu, uw, srcq0);
            uint32_t xB = __shfl_sync(0xffffffffu, ux, srcq1);
            uint32_t yB = __shfl_sync(0xffffffffu, uy, srcq1);
            uint32_t zB = __shfl_sync(0xffffffffu, uz, srcq1);
            uint32_t wB = __shfl_sync(0xffffffffu, uw, srcq1);
            uint32_t a0 = odd ? yA : xA;
            uint32_t a1 = odd ? wA : zA;
            uint32_t a2 = odd ? yB : xB;
            uint32_t a3 = odd ? wB : zB;
            #pragma unroll
            for (int ns2 = 0; ns2 < 8; ns2++) {
                uint32_t b0 = Vs[(ns * 8 + t) * KLDV + ns2 * 8 + g];
                uint32_t b1 = Vs[(ns * 8 + t + 4) * KLDV + ns2 * 8 + g];
                mma8(acc_o[ns2], a0, a1, a2, a3, b0, b1);
            }
        }
    }

    float llo = lsum_lo;
    llo += __shfl_xor_sync(0xffffffffu, llo, 1);
    llo += __shfl_xor_sync(0xffffffffu, llo, 2);
    float lhi = lsum_hi;
    lhi += __shfl_xor_sync(0xffffffffu, lhi, 1);
    lhi += __shfl_xor_sync(0xffffffffu, lhi, 2);

    float* baseo = g_Op + (((size_t)chunk * Bb + b) * Tt + qrow_lo) * HS;
    #pragma unroll
    for (int ns2 = 0; ns2 < 8; ns2++) {
        *(float2*)(baseo + ns2 * 8 + 2 * t)          = make_float2(acc_o[ns2].x, acc_o[ns2].y);
        *(float2*)(baseo + 8 * HS + ns2 * 8 + 2 * t) = make_float2(acc_o[ns2].z, acc_o[ns2].w);
    }
    if (t == 0) {
        g_Lp[((size_t)chunk * Bb + b) * Tt + qrow_lo] = llo;
        g_Lp[((size_t)chunk * Bb + b) * Tt + qrow_hi] = lhi;
    }
}

// ============================================================================
// Combine (R8): float4/thread, <=4 slots.
// ============================================================================
__global__ __launch_bounds__(256) void attn_combine(float* __restrict__ out)
{
    const int idx4 = blockIdx.x * 256 + threadIdx.x;
    const int row  = idx4 >> 4;
    const int d4   = (idx4 & 15) * 4;
    const int trow = row & (Tt - 1);
    const int b    = row >> 11;
    const int rb   = trow >> 7;
    const int nch  = (rb + CH) >> 2;

    float4 o = make_float4(0.f, 0.f, 0.f, 0.f);
    float l = 0.f;
    #pragma unroll
    for (int s = 0; s < NSLOT; s++) {
        if (s < nch) {
            float4 v = *(const float4*)(g_Op + (((size_t)s * Bb + b) * Tt + trow) * HS + d4);
            o.x += v.x; o.y += v.y; o.z += v.z; o.w += v.w;
            l += g_Lp[((size_t)s * Bb + b) * Tt + trow];
        }
    }
    const float rl = 1.0f / l;
    *(float4*)(out + (size_t)row * HS + d4) =
        make_float4(o.x * rl, o.y * rl, o.z * rl, o.w * rl);
}

// ============================================================================
extern "C" void kernel_launch(void* const* d_in, const int* in_sizes, int n_in,
                              void* d_out, int out_size)
{
    const float* x  = (const float*)d_in[0];
    const float* Wq = (const float*)d_in[1];
    const float* Wk = (const float*)d_in[2];
    const float* Wv = (const float*)d_in[3];
    float* out = (float*)d_out;

    prep_b<<<64, 256>>>(Wq, Wk, Wv);
    qkv_mma<<<(Bb * Tt) / 64, 256>>>(x);

    cudaFuncSetAttribute(attn_part, cudaFuncAttributeMaxDynamicSharedMemorySize, SMEM_ATTN);
    attn_part<<<Bb * WPB, 256, SMEM_ATTN>>>();

    attn_combine<<<(Bb * Tt * (HS / 4)) / 256, 256>>>(out);
}